// round 1
// baseline (speedup 1.0000x reference)
#include <cuda_runtime.h>
#include <math.h>

// Problem constants
#define B_   4
#define T_   2048
#define D_   512
#define BT_  8192
#define H_   8
#define KVH_ 2
#define HD_  64
#define DN_  32
#define DR_  32

// ---------------------------------------------------------------------------
// Scratch buffers (device globals; no allocation allowed)
// ---------------------------------------------------------------------------
__device__ __align__(256) float g_cq  [BT_ * 256];   // id 0
__device__ __align__(256) float g_ckv [BT_ * 128];   // id 1
__device__ __align__(256) float g_kr  [BT_ * 64];    // id 2
__device__ __align__(256) float g_vres[BT_ * 512];   // id 3
__device__ __align__(256) float g_qn  [BT_ * 256];   // id 4
__device__ __align__(256) float g_qr  [BT_ * 256];   // id 5
__device__ __align__(256) float g_kn  [BT_ * 64];    // id 6
__device__ __align__(256) float g_v   [BT_ * 128];   // id 7
__device__ __align__(256) float g_q   [B_ * H_ * T_ * HD_];    // id 8
__device__ __align__(256) float g_k   [B_ * KVH_ * T_ * HD_];  // id 9
__device__ __align__(256) float g_attn[BT_ * 512];   // id 10

__device__ __forceinline__ float* bufp(int id) {
    switch (id) {
        case 0:  return g_cq;
        case 1:  return g_ckv;
        case 2:  return g_kr;
        case 3:  return g_vres;
        case 4:  return g_qn;
        case 5:  return g_qr;
        case 6:  return g_kn;
        case 7:  return g_v;
        case 8:  return g_q;
        case 9:  return g_k;
        default: return g_attn;
    }
}

// ---------------------------------------------------------------------------
// Tiled fp32 GEMM: C[M,N] = A[M,K] @ B[K,N] (all row-major)
// BM=128, BN=64, BK=16, 256 threads, 8x4 per-thread tile.
// Requires M%128==0, N%64==0, K%16==0 (true for all call sites).
// ---------------------------------------------------------------------------
__global__ void __launch_bounds__(256) gemm_kernel(
    const float* __restrict__ Ap, int Aid,
    const float* __restrict__ Bm,
    float* Cp, int Cid,
    int M, int N, int K)
{
    const float* A = (Aid >= 0) ? bufp(Aid) : Ap;
    float*       C = (Cid >= 0) ? bufp(Cid) : Cp;

    __shared__ __align__(16) float As[16][128];
    __shared__ __align__(16) float Bs[16][64];

    const int bm = blockIdx.y * 128;
    const int bn = blockIdx.x * 64;
    const int tid = threadIdx.x;
    const int ty = tid >> 4;    // 0..15
    const int tx = tid & 15;    // 0..15

    float4 acc[8];
#pragma unroll
    for (int i = 0; i < 8; i++) acc[i] = make_float4(0.f, 0.f, 0.f, 0.f);

    for (int k0 = 0; k0 < K; k0 += 16) {
        // Load A tile (128x16) -> As transposed [k][m]
#pragma unroll
        for (int i = 0; i < 2; i++) {
            int id4 = tid + i * 256;            // float4 index 0..511
            int r   = id4 >> 2;                 // row 0..127
            int c4  = (id4 & 3) * 4;            // col 0,4,8,12
            float4 v = *(const float4*)&A[(size_t)(bm + r) * K + k0 + c4];
            As[c4 + 0][r] = v.x;
            As[c4 + 1][r] = v.y;
            As[c4 + 2][r] = v.z;
            As[c4 + 3][r] = v.w;
        }
        // Load B tile (16x64)
        {
            int r  = tid >> 4;                  // 0..15
            int c4 = (tid & 15) * 4;            // 0..60
            *(float4*)&Bs[r][c4] = *(const float4*)&Bm[(size_t)(k0 + r) * N + bn + c4];
        }
        __syncthreads();

#pragma unroll
        for (int kk = 0; kk < 16; kk++) {
            float a[8];
            *(float4*)&a[0] = *(const float4*)&As[kk][ty * 8];
            *(float4*)&a[4] = *(const float4*)&As[kk][ty * 8 + 4];
            float4 b = *(const float4*)&Bs[kk][tx * 4];
#pragma unroll
            for (int i = 0; i < 8; i++) {
                acc[i].x = fmaf(a[i], b.x, acc[i].x);
                acc[i].y = fmaf(a[i], b.y, acc[i].y);
                acc[i].z = fmaf(a[i], b.z, acc[i].z);
                acc[i].w = fmaf(a[i], b.w, acc[i].w);
            }
        }
        __syncthreads();
    }

#pragma unroll
    for (int i = 0; i < 8; i++) {
        *(float4*)&C[(size_t)(bm + ty * 8 + i) * N + bn + tx * 4] = acc[i];
    }
}

// ---------------------------------------------------------------------------
// In-place RMSNorm over last dim N (N = 256 or 128), one block per row.
// ---------------------------------------------------------------------------
__global__ void __launch_bounds__(128) rmsnorm_kernel(int bufid, const float* __restrict__ w, int N)
{
    float* x = bufp(bufid) + (size_t)blockIdx.x * N;
    int tid = threadIdx.x;

    float ss = 0.f;
    for (int i = tid; i < N; i += 128) { float v = x[i]; ss = fmaf(v, v, ss); }
#pragma unroll
    for (int o = 16; o; o >>= 1) ss += __shfl_xor_sync(0xffffffffu, ss, o);

    __shared__ float sp[4];
    if ((tid & 31) == 0) sp[tid >> 5] = ss;
    __syncthreads();
    float tot = sp[0] + sp[1] + sp[2] + sp[3];
    float sc = rsqrtf(tot / (float)N + 1e-6f);

    for (int i = tid; i < N; i += 128) x[i] = x[i] * sc * w[i];
}

// ---------------------------------------------------------------------------
// Rope helper: angle for rope-dim index dr in [0,32) at position t
// ---------------------------------------------------------------------------
__device__ __forceinline__ void rope_cs(int t, int dr, float& c, float& s)
{
    int j = dr & 15;
    float inv = 1.0f / powf(500000.0f, (float)(2 * j) * (1.0f / 32.0f));
    float ang = (float)t * inv;
    sincosf(ang, &s, &c);
}

// ---------------------------------------------------------------------------
// Assemble Q: concat(q_nope, rope(q_rope)) -> per-head RMSNorm -> g_q[B,H,T,64]
// One block per token, 512 threads (8 heads x 64 dims).
// ---------------------------------------------------------------------------
__global__ void __launch_bounds__(512) assemble_q_kernel(const float* __restrict__ hw)
{
    int token = blockIdx.x;
    int b = token >> 11;
    int t = token & 2047;
    int tid = threadIdx.x;
    int h = tid >> 6;
    int d = tid & 63;

    const float* qn = g_qn + (size_t)token * 256 + h * 32;
    const float* qr = g_qr + (size_t)token * 256 + h * 32;

    float val;
    if (d < DN_) {
        val = qn[d];
    } else {
        int dr = d - DN_;
        float c, s;
        rope_cs(t, dr, c, s);
        val = (dr < 16) ? (qr[dr] * c - qr[dr + 16] * s)
                        : (qr[dr] * c + qr[dr - 16] * s);
    }

    float ss = val * val;
#pragma unroll
    for (int o = 16; o; o >>= 1) ss += __shfl_xor_sync(0xffffffffu, ss, o);
    __shared__ float sp[16];
    if ((tid & 31) == 0) sp[tid >> 5] = ss;
    __syncthreads();
    float tot = sp[2 * h] + sp[2 * h + 1];
    float sc = rsqrtf(tot * (1.0f / 64.0f) + 1e-6f);

    g_q[((size_t)(b * H_ + h) * T_ + t) * HD_ + d] = val * sc * hw[d];
}

// ---------------------------------------------------------------------------
// Assemble K: concat(k_nope, rope(k_rope)) -> per-head RMSNorm -> g_k[B,KVH,T,64]
// One block per token, 128 threads (2 kv-heads x 64 dims).
// ---------------------------------------------------------------------------
__global__ void __launch_bounds__(128) assemble_k_kernel(const float* __restrict__ hw)
{
    int token = blockIdx.x;
    int b = token >> 11;
    int t = token & 2047;
    int tid = threadIdx.x;
    int h = tid >> 6;     // kv head 0..1
    int d = tid & 63;

    const float* kn = g_kn + (size_t)token * 64 + h * 32;
    const float* kr = g_kr + (size_t)token * 64 + h * 32;

    float val;
    if (d < DN_) {
        val = kn[d];
    } else {
        int dr = d - DN_;
        float c, s;
        rope_cs(t, dr, c, s);
        val = (dr < 16) ? (kr[dr] * c - kr[dr + 16] * s)
                        : (kr[dr] * c + kr[dr - 16] * s);
    }

    float ss = val * val;
#pragma unroll
    for (int o = 16; o; o >>= 1) ss += __shfl_xor_sync(0xffffffffu, ss, o);
    __shared__ float sp[4];
    if ((tid & 31) == 0) sp[tid >> 5] = ss;
    __syncthreads();
    float tot = sp[2 * h] + sp[2 * h + 1];
    float sc = rsqrtf(tot * (1.0f / 64.0f) + 1e-6f);

    g_k[((size_t)(b * KVH_ + h) * T_ + t) * HD_ + d] = val * sc * hw[d];
}

// ---------------------------------------------------------------------------
// Flash attention (fp32, causal, GQA) + fused value-residual add.
// grid: (T/128, B*H), block: 128 threads. Thread = one query row.
// Writes g_attn[B,T,H*64] ready for the output GEMM.
// ---------------------------------------------------------------------------
#define FBM 128
#define FBN 32

__global__ void __launch_bounds__(128) flash_kernel()
{
    __shared__ float q_sh[64 * FBM];                      // transposed [d][row], 32 KB
    __shared__ __align__(16) float k_sh[FBN][64];         // 8 KB
    __shared__ __align__(16) float v_sh[FBN][64];         // 8 KB

    const int bh = blockIdx.y;
    const int b = bh >> 3;
    const int h = bh & 7;
    const int kvh = h >> 2;                               // GQA group of 4
    const int qs = blockIdx.x * FBM;
    const int tid = threadIdx.x;

    const float* qbase = g_q + ((size_t)(b * H_ + h) * T_ + qs) * 64;
    const float* kbase = g_k + ((size_t)(b * KVH_ + kvh) * T_) * 64;
    const float* vbase = g_v + ((size_t)b * T_ * (KVH_ * HD_)) + kvh * 64;

    // Stage Q tile transposed (coalesced global reads)
    for (int idx = tid; idx < FBM * 64; idx += 128) {
        int r = idx >> 6, d = idx & 63;
        q_sh[d * FBM + r] = qbase[idx];
    }
    __syncthreads();

    const int tq = qs + tid;
    float m = -1e30f, l = 0.f;
    float acc[64];
#pragma unroll
    for (int i = 0; i < 64; i++) acc[i] = 0.f;

    const int kend = qs + FBM;
    for (int ks = 0; ks < kend; ks += FBN) {
        // Load K/V tiles (float4, coalesced)
        for (int idx = tid; idx < FBN * 16; idx += 128) {
            int r = idx >> 4, c = (idx & 15) * 4;
            *(float4*)&k_sh[r][c] = *(const float4*)&kbase[(size_t)(ks + r) * 64 + c];
            *(float4*)&v_sh[r][c] = *(const float4*)&vbase[(size_t)(ks + r) * (KVH_ * HD_) + c];
        }
        __syncthreads();

        // Scores: s[j] = q . k_j
        float s[FBN];
#pragma unroll
        for (int j = 0; j < FBN; j++) s[j] = 0.f;

        for (int d0 = 0; d0 < 64; d0 += 4) {
            float q0 = q_sh[(d0 + 0) * FBM + tid];
            float q1 = q_sh[(d0 + 1) * FBM + tid];
            float q2 = q_sh[(d0 + 2) * FBM + tid];
            float q3 = q_sh[(d0 + 3) * FBM + tid];
#pragma unroll
            for (int j = 0; j < FBN; j++) {
                float4 kv = *(const float4*)&k_sh[j][d0];
                s[j] = fmaf(q0, kv.x, fmaf(q1, kv.y, fmaf(q2, kv.z, fmaf(q3, kv.w, s[j]))));
            }
        }

        // Causal mask + scale + running max
        float mnew = m;
#pragma unroll
        for (int j = 0; j < FBN; j++) {
            s[j] = (ks + j <= tq) ? s[j] * 0.125f : -1e30f;
            mnew = fmaxf(mnew, s[j]);
        }

        float corr = expf(m - mnew);
        l *= corr;
#pragma unroll
        for (int i = 0; i < 64; i++) acc[i] *= corr;

#pragma unroll
        for (int j = 0; j < FBN; j++) {
            float p = expf(s[j] - mnew);
            l += p;
#pragma unroll
            for (int d0 = 0; d0 < 64; d0 += 4) {
                float4 vv = *(const float4*)&v_sh[j][d0];
                acc[d0 + 0] = fmaf(p, vv.x, acc[d0 + 0]);
                acc[d0 + 1] = fmaf(p, vv.y, acc[d0 + 1]);
                acc[d0 + 2] = fmaf(p, vv.z, acc[d0 + 2]);
                acc[d0 + 3] = fmaf(p, vv.w, acc[d0 + 3]);
            }
        }
        m = mnew;
        __syncthreads();
    }

    // Epilogue: normalize + value-residual add, write [B,T,H*64]
    const float inv_l = 1.0f / l;
    float* outp = g_attn + ((size_t)b * T_ + tq) * 512 + h * 64;
    const float* vr = g_vres + ((size_t)b * T_ + tq) * 512 + h * 64;
#pragma unroll
    for (int d0 = 0; d0 < 64; d0 += 4) {
        float4 r = *(const float4*)&vr[d0];
        float4 o;
        o.x = fmaf(acc[d0 + 0], inv_l, r.x);
        o.y = fmaf(acc[d0 + 1], inv_l, r.y);
        o.z = fmaf(acc[d0 + 2], inv_l, r.z);
        o.w = fmaf(acc[d0 + 3], inv_l, r.w);
        *(float4*)&outp[d0] = o;
    }
}

// ---------------------------------------------------------------------------
// Launch
// ---------------------------------------------------------------------------
extern "C" void kernel_launch(void* const* d_in, const int* in_sizes, int n_in,
                              void* d_out, int out_size)
{
    const float* x       = (const float*)d_in[0];
    const float* W_DQ    = (const float*)d_in[1];
    const float* W_UQ    = (const float*)d_in[2];
    const float* W_QR    = (const float*)d_in[3];
    const float* W_DKV   = (const float*)d_in[4];
    const float* W_UK    = (const float*)d_in[5];
    const float* W_UV    = (const float*)d_in[6];
    const float* W_KR    = (const float*)d_in[7];
    const float* W_VR    = (const float*)d_in[8];
    const float* W_O     = (const float*)d_in[9];
    const float* q_ln_w  = (const float*)d_in[10];
    const float* kv_ln_w = (const float*)d_in[11];
    const float* q_hw    = (const float*)d_in[12];
    const float* k_hw    = (const float*)d_in[13];
    float* out = (float*)d_out;

    // Stage 1: projections from x
    gemm_kernel<<<dim3(256 / 64, BT_ / 128), 256>>>(x, -1, W_DQ,  nullptr, 0, BT_, 256, 512);
    gemm_kernel<<<dim3(128 / 64, BT_ / 128), 256>>>(x, -1, W_DKV, nullptr, 1, BT_, 128, 512);
    gemm_kernel<<<dim3( 64 / 64, BT_ / 128), 256>>>(x, -1, W_KR,  nullptr, 2, BT_,  64, 512);
    gemm_kernel<<<dim3(512 / 64, BT_ / 128), 256>>>(x, -1, W_VR,  nullptr, 3, BT_, 512, 512);

    // Stage 2: latent RMSNorms (in place)
    rmsnorm_kernel<<<BT_, 128>>>(0, q_ln_w, 256);
    rmsnorm_kernel<<<BT_, 128>>>(1, kv_ln_w, 128);

    // Stage 3: up-projections
    gemm_kernel<<<dim3(256 / 64, BT_ / 128), 256>>>(nullptr, 0, W_UQ, nullptr, 4, BT_, 256, 256);
    gemm_kernel<<<dim3(256 / 64, BT_ / 128), 256>>>(nullptr, 0, W_QR, nullptr, 5, BT_, 256, 256);
    gemm_kernel<<<dim3( 64 / 64, BT_ / 128), 256>>>(nullptr, 1, W_UK, nullptr, 6, BT_,  64, 128);
    gemm_kernel<<<dim3(128 / 64, BT_ / 128), 256>>>(nullptr, 1, W_UV, nullptr, 7, BT_, 128, 128);

    // Stage 4: rope + head-norm + layout
    assemble_q_kernel<<<BT_, 512>>>(q_hw);
    assemble_k_kernel<<<BT_, 128>>>(k_hw);

    // Stage 5: causal flash attention + value residual
    flash_kernel<<<dim3(T_ / FBM, B_ * H_), 128>>>();

    // Stage 6: output projection -> d_out
    gemm_kernel<<<dim3(512 / 64, BT_ / 128), 256>>>(nullptr, 10, W_O, out, -1, BT_, 512, 512);
}

// round 3
// speedup vs baseline: 1.0214x; 1.0214x over previous
#include <cuda_runtime.h>
#include <cuda_bf16.h>
#include <math.h>
#include <cstdint>

// Problem constants
#define B_   4
#define T_   2048
#define D_   512
#define BT_  8192
#define H_   8
#define KVH_ 2
#define HD_  64
#define DN_  32
#define DR_  32

// ---------------------------------------------------------------------------
// Scratch buffers (device globals; no allocation allowed)
// ---------------------------------------------------------------------------
__device__ __align__(256) float g_cq  [BT_ * 256];   // id 0
__device__ __align__(256) float g_ckv [BT_ * 128];   // id 1
__device__ __align__(256) float g_kr  [BT_ * 64];    // id 2
__device__ __align__(256) float g_vres[BT_ * 512];   // id 3
__device__ __align__(256) float g_qn  [BT_ * 256];   // id 4
__device__ __align__(256) float g_qr  [BT_ * 256];   // id 5
__device__ __align__(256) float g_kn  [BT_ * 64];    // id 6
__device__ __align__(256) float g_v   [BT_ * 128];   // id 7
__device__ __align__(256) float g_q   [B_ * H_ * T_ * HD_];    // id 8
__device__ __align__(256) float g_k   [B_ * KVH_ * T_ * HD_];  // id 9
__device__ __align__(256) float g_attn[BT_ * 512];   // id 10

__device__ __forceinline__ float* bufp(int id) {
    switch (id) {
        case 0:  return g_cq;
        case 1:  return g_ckv;
        case 2:  return g_kr;
        case 3:  return g_vres;
        case 4:  return g_qn;
        case 5:  return g_qr;
        case 6:  return g_kn;
        case 7:  return g_v;
        case 8:  return g_q;
        case 9:  return g_k;
        default: return g_attn;
    }
}

// ---------------------------------------------------------------------------
// mma.sync bf16 (m16n8k16), fp32 accumulate, row(A) x col(B)
// ---------------------------------------------------------------------------
__device__ __forceinline__ void mma16816(float* c, const uint32_t* a, const uint32_t* b) {
    asm volatile(
        "mma.sync.aligned.m16n8k16.row.col.f32.bf16.bf16.f32 "
        "{%0,%1,%2,%3}, {%4,%5,%6,%7}, {%8,%9}, {%0,%1,%2,%3};"
        : "+f"(c[0]), "+f"(c[1]), "+f"(c[2]), "+f"(c[3])
        : "r"(a[0]), "r"(a[1]), "r"(a[2]), "r"(a[3]), "r"(b[0]), "r"(b[1]));
}

// ---------------------------------------------------------------------------
// Tensor-core GEMM with bf16 hi/lo split: C[M,N] = A[M,K] @ B[K,N], fp32 rm.
// Block 128x64, BK=32, 256 threads (8 warps: 4 in M x 2 in N, warp tile 32x32).
// Requires M%128==0, N%64==0, K%32==0 (true for all call sites).
// ---------------------------------------------------------------------------
#define GBM 128
#define GBN 64
#define GBK 32
#define APAD 4
#define ASTR (GBK + APAD)   // 36 bf16 -> 72B row stride (conflict-free frag loads)

__global__ void __launch_bounds__(256) gemm_mma(
    const float* __restrict__ Ap, int Aid,
    const float* __restrict__ Bm,
    float* Cp, int Cid,
    int M, int N, int K)
{
    const float* A = (Aid >= 0) ? bufp(Aid) : Ap;
    float*       C = (Cid >= 0) ? bufp(Cid) : Cp;

    __shared__ __nv_bfloat16 Ah[GBM][ASTR];
    __shared__ __nv_bfloat16 Al[GBM][ASTR];
    __shared__ __nv_bfloat16 Bh[GBN][ASTR];   // stored [n][k]
    __shared__ __nv_bfloat16 Bl[GBN][ASTR];

    const int bm   = blockIdx.y * GBM;
    const int bn   = blockIdx.x * GBN;
    const int tid  = threadIdx.x;
    const int warp = tid >> 5;
    const int lane = tid & 31;
    const int wm   = (warp & 3) * 32;   // warp M offset
    const int wn   = (warp >> 2) * 32;  // warp N offset
    const int grp  = lane >> 2;         // 0..7
    const int tig  = lane & 3;          // 0..3

    float acc[2][4][4];
#pragma unroll
    for (int mi = 0; mi < 2; mi++)
#pragma unroll
        for (int ni = 0; ni < 4; ni++)
#pragma unroll
            for (int i = 0; i < 4; i++) acc[mi][ni][i] = 0.f;

    for (int k0 = 0; k0 < K; k0 += GBK) {
        // Stage A tile: 128x32 fp32 -> hi/lo bf16 (float2 per thread iter)
        for (int idx = tid; idx < GBM * (GBK / 2); idx += 256) {
            int r  = idx >> 4;
            int c2 = (idx & 15) * 2;
            float2 v = *(const float2*)&A[(size_t)(bm + r) * K + k0 + c2];
            __nv_bfloat16 hx = __float2bfloat16(v.x);
            __nv_bfloat16 hy = __float2bfloat16(v.y);
            __nv_bfloat162 h; h.x = hx; h.y = hy;
            __nv_bfloat162 l;
            l.x = __float2bfloat16(v.x - __bfloat162float(hx));
            l.y = __float2bfloat16(v.y - __bfloat162float(hy));
            *(__nv_bfloat162*)&Ah[r][c2] = h;
            *(__nv_bfloat162*)&Al[r][c2] = l;
        }
        // Stage B tile: 32x64 fp32 -> transposed [n][k] hi/lo bf16
        for (int idx = tid; idx < GBK * (GBN / 2); idx += 256) {
            int k  = idx >> 5;
            int n2 = (idx & 31) * 2;
            float2 v = *(const float2*)&Bm[(size_t)(k0 + k) * N + bn + n2];
            __nv_bfloat16 h0 = __float2bfloat16(v.x);
            __nv_bfloat16 h1 = __float2bfloat16(v.y);
            Bh[n2][k]     = h0;
            Bh[n2 + 1][k] = h1;
            Bl[n2][k]     = __float2bfloat16(v.x - __bfloat162float(h0));
            Bl[n2 + 1][k] = __float2bfloat16(v.y - __bfloat162float(h1));
        }
        __syncthreads();

#pragma unroll
        for (int ks = 0; ks < GBK; ks += 16) {
            uint32_t ah[2][4], al[2][4], bh[4][2], bl[4][2];
#pragma unroll
            for (int mi = 0; mi < 2; mi++) {
                int r0 = wm + mi * 16 + grp;
                int c0 = ks + tig * 2;
                ah[mi][0] = *(const uint32_t*)&Ah[r0][c0];
                ah[mi][1] = *(const uint32_t*)&Ah[r0 + 8][c0];
                ah[mi][2] = *(const uint32_t*)&Ah[r0][c0 + 8];
                ah[mi][3] = *(const uint32_t*)&Ah[r0 + 8][c0 + 8];
                al[mi][0] = *(const uint32_t*)&Al[r0][c0];
                al[mi][1] = *(const uint32_t*)&Al[r0 + 8][c0];
                al[mi][2] = *(const uint32_t*)&Al[r0][c0 + 8];
                al[mi][3] = *(const uint32_t*)&Al[r0 + 8][c0 + 8];
            }
#pragma unroll
            for (int ni = 0; ni < 4; ni++) {
                int n0 = wn + ni * 8 + grp;
                int c0 = ks + tig * 2;
                bh[ni][0] = *(const uint32_t*)&Bh[n0][c0];
                bh[ni][1] = *(const uint32_t*)&Bh[n0][c0 + 8];
                bl[ni][0] = *(const uint32_t*)&Bl[n0][c0];
                bl[ni][1] = *(const uint32_t*)&Bl[n0][c0 + 8];
            }
#pragma unroll
            for (int mi = 0; mi < 2; mi++)
#pragma unroll
                for (int ni = 0; ni < 4; ni++) {
                    mma16816(acc[mi][ni], ah[mi], bh[ni]);
                    mma16816(acc[mi][ni], ah[mi], bl[ni]);
                    mma16816(acc[mi][ni], al[mi], bh[ni]);
                }
        }
        __syncthreads();
    }

    // Epilogue: c0,c1 -> (row, col..col+1); c2,c3 -> (row+8, col..col+1)
#pragma unroll
    for (int mi = 0; mi < 2; mi++) {
#pragma unroll
        for (int ni = 0; ni < 4; ni++) {
            int row = bm + wm + mi * 16 + grp;
            int col = bn + wn + ni * 8 + tig * 2;
            float2 v0 = make_float2(acc[mi][ni][0], acc[mi][ni][1]);
            float2 v1 = make_float2(acc[mi][ni][2], acc[mi][ni][3]);
            *(float2*)&C[(size_t)row * N + col]       = v0;
            *(float2*)&C[(size_t)(row + 8) * N + col] = v1;
        }
    }
}

// ---------------------------------------------------------------------------
// In-place RMSNorm over last dim N (N = 256 or 128), one block per row.
// ---------------------------------------------------------------------------
__global__ void __launch_bounds__(128) rmsnorm_kernel(int bufid, const float* __restrict__ w, int N)
{
    float* x = bufp(bufid) + (size_t)blockIdx.x * N;
    int tid = threadIdx.x;

    float ss = 0.f;
    for (int i = tid; i < N; i += 128) { float v = x[i]; ss = fmaf(v, v, ss); }
#pragma unroll
    for (int o = 16; o; o >>= 1) ss += __shfl_xor_sync(0xffffffffu, ss, o);

    __shared__ float sp[4];
    if ((tid & 31) == 0) sp[tid >> 5] = ss;
    __syncthreads();
    float tot = sp[0] + sp[1] + sp[2] + sp[3];
    float sc = rsqrtf(tot / (float)N + 1e-6f);

    for (int i = tid; i < N; i += 128) x[i] = x[i] * sc * w[i];
}

// ---------------------------------------------------------------------------
// Rope helper
// ---------------------------------------------------------------------------
__device__ __forceinline__ void rope_cs(int t, int dr, float& c, float& s)
{
    int j = dr & 15;
    float inv = 1.0f / powf(500000.0f, (float)(2 * j) * (1.0f / 32.0f));
    float ang = (float)t * inv;
    sincosf(ang, &s, &c);
}

// ---------------------------------------------------------------------------
// Assemble Q: concat(q_nope, rope(q_rope)) -> per-head RMSNorm -> g_q[B,H,T,64]
// ---------------------------------------------------------------------------
__global__ void __launch_bounds__(512) assemble_q_kernel(const float* __restrict__ hw)
{
    int token = blockIdx.x;
    int b = token >> 11;
    int t = token & 2047;
    int tid = threadIdx.x;
    int h = tid >> 6;
    int d = tid & 63;

    const float* qn = g_qn + (size_t)token * 256 + h * 32;
    const float* qr = g_qr + (size_t)token * 256 + h * 32;

    float val;
    if (d < DN_) {
        val = qn[d];
    } else {
        int dr = d - DN_;
        float c, s;
        rope_cs(t, dr, c, s);
        val = (dr < 16) ? (qr[dr] * c - qr[dr + 16] * s)
                        : (qr[dr] * c + qr[dr - 16] * s);
    }

    float ss = val * val;
#pragma unroll
    for (int o = 16; o; o >>= 1) ss += __shfl_xor_sync(0xffffffffu, ss, o);
    __shared__ float sp[16];
    if ((tid & 31) == 0) sp[tid >> 5] = ss;
    __syncthreads();
    float tot = sp[2 * h] + sp[2 * h + 1];
    float sc = rsqrtf(tot * (1.0f / 64.0f) + 1e-6f);

    g_q[((size_t)(b * H_ + h) * T_ + t) * HD_ + d] = val * sc * hw[d];
}

// ---------------------------------------------------------------------------
// Assemble K
// ---------------------------------------------------------------------------
__global__ void __launch_bounds__(128) assemble_k_kernel(const float* __restrict__ hw)
{
    int token = blockIdx.x;
    int b = token >> 11;
    int t = token & 2047;
    int tid = threadIdx.x;
    int h = tid >> 6;     // kv head 0..1
    int d = tid & 63;

    const float* kn = g_kn + (size_t)token * 64 + h * 32;
    const float* kr = g_kr + (size_t)token * 64 + h * 32;

    float val;
    if (d < DN_) {
        val = kn[d];
    } else {
        int dr = d - DN_;
        float c, s;
        rope_cs(t, dr, c, s);
        val = (dr < 16) ? (kr[dr] * c - kr[dr + 16] * s)
                        : (kr[dr] * c + kr[dr - 16] * s);
    }

    float ss = val * val;
#pragma unroll
    for (int o = 16; o; o >>= 1) ss += __shfl_xor_sync(0xffffffffu, ss, o);
    __shared__ float sp[4];
    if ((tid & 31) == 0) sp[tid >> 5] = ss;
    __syncthreads();
    float tot = sp[2 * h] + sp[2 * h + 1];
    float sc = rsqrtf(tot * (1.0f / 64.0f) + 1e-6f);

    g_k[((size_t)(b * KVH_ + h) * T_ + t) * HD_ + d] = val * sc * hw[d];
}

// ---------------------------------------------------------------------------
// Flash attention (fp32, causal, GQA) + fused value-residual add.
// grid: (T/128, B*H), block: 128 threads. Thread = one query row.
// ---------------------------------------------------------------------------
#define FBM 128
#define FBN 32

__global__ void __launch_bounds__(128) flash_kernel()
{
    __shared__ float q_sh[64 * FBM];                      // transposed [d][row], 32 KB
    __shared__ __align__(16) float k_sh[FBN][64];         // 8 KB
    __shared__ __align__(16) float v_sh[FBN][64];         // 8 KB

    const int bh = blockIdx.y;
    const int b = bh >> 3;
    const int h = bh & 7;
    const int kvh = h >> 2;                               // GQA group of 4
    const int qs = blockIdx.x * FBM;
    const int tid = threadIdx.x;

    const float* qbase = g_q + ((size_t)(b * H_ + h) * T_ + qs) * 64;
    const float* kbase = g_k + ((size_t)(b * KVH_ + kvh) * T_) * 64;
    const float* vbase = g_v + ((size_t)b * T_ * (KVH_ * HD_)) + kvh * 64;

    for (int idx = tid; idx < FBM * 64; idx += 128) {
        int r = idx >> 6, d = idx & 63;
        q_sh[d * FBM + r] = qbase[idx];
    }
    __syncthreads();

    const int tq = qs + tid;
    float m = -1e30f, l = 0.f;
    float acc[64];
#pragma unroll
    for (int i = 0; i < 64; i++) acc[i] = 0.f;

    const int kend = qs + FBM;
    for (int ks = 0; ks < kend; ks += FBN) {
        for (int idx = tid; idx < FBN * 16; idx += 128) {
            int r = idx >> 4, c = (idx & 15) * 4;
            *(float4*)&k_sh[r][c] = *(const float4*)&kbase[(size_t)(ks + r) * 64 + c];
            *(float4*)&v_sh[r][c] = *(const float4*)&vbase[(size_t)(ks + r) * (KVH_ * HD_) + c];
        }
        __syncthreads();

        float s[FBN];
#pragma unroll
        for (int j = 0; j < FBN; j++) s[j] = 0.f;

        for (int d0 = 0; d0 < 64; d0 += 4) {
            float q0 = q_sh[(d0 + 0) * FBM + tid];
            float q1 = q_sh[(d0 + 1) * FBM + tid];
            float q2 = q_sh[(d0 + 2) * FBM + tid];
            float q3 = q_sh[(d0 + 3) * FBM + tid];
#pragma unroll
            for (int j = 0; j < FBN; j++) {
                float4 kv = *(const float4*)&k_sh[j][d0];
                s[j] = fmaf(q0, kv.x, fmaf(q1, kv.y, fmaf(q2, kv.z, fmaf(q3, kv.w, s[j]))));
            }
        }

        float mnew = m;
#pragma unroll
        for (int j = 0; j < FBN; j++) {
            s[j] = (ks + j <= tq) ? s[j] * 0.125f : -1e30f;
            mnew = fmaxf(mnew, s[j]);
        }

        float corr = __expf(m - mnew);
        l *= corr;
#pragma unroll
        for (int i = 0; i < 64; i++) acc[i] *= corr;

#pragma unroll
        for (int j = 0; j < FBN; j++) {
            float p = __expf(s[j] - mnew);
            l += p;
#pragma unroll
            for (int d0 = 0; d0 < 64; d0 += 4) {
                float4 vv = *(const float4*)&v_sh[j][d0];
                acc[d0 + 0] = fmaf(p, vv.x, acc[d0 + 0]);
                acc[d0 + 1] = fmaf(p, vv.y, acc[d0 + 1]);
                acc[d0 + 2] = fmaf(p, vv.z, acc[d0 + 2]);
                acc[d0 + 3] = fmaf(p, vv.w, acc[d0 + 3]);
            }
        }
        m = mnew;
        __syncthreads();
    }

    const float inv_l = 1.0f / l;
    float* outp = g_attn + ((size_t)b * T_ + tq) * 512 + h * 64;
    const float* vr = g_vres + ((size_t)b * T_ + tq) * 512 + h * 64;
#pragma unroll
    for (int d0 = 0; d0 < 64; d0 += 4) {
        float4 r = *(const float4*)&vr[d0];
        float4 o;
        o.x = fmaf(acc[d0 + 0], inv_l, r.x);
        o.y = fmaf(acc[d0 + 1], inv_l, r.y);
        o.z = fmaf(acc[d0 + 2], inv_l, r.z);
        o.w = fmaf(acc[d0 + 3], inv_l, r.w);
        *(float4*)&outp[d0] = o;
    }
}

// ---------------------------------------------------------------------------
// Launch
// ---------------------------------------------------------------------------
extern "C" void kernel_launch(void* const* d_in, const int* in_sizes, int n_in,
                              void* d_out, int out_size)
{
    const float* x       = (const float*)d_in[0];
    const float* W_DQ    = (const float*)d_in[1];
    const float* W_UQ    = (const float*)d_in[2];
    const float* W_QR    = (const float*)d_in[3];
    const float* W_DKV   = (const float*)d_in[4];
    const float* W_UK    = (const float*)d_in[5];
    const float* W_UV    = (const float*)d_in[6];
    const float* W_KR    = (const float*)d_in[7];
    const float* W_VR    = (const float*)d_in[8];
    const float* W_O     = (const float*)d_in[9];
    const float* q_ln_w  = (const float*)d_in[10];
    const float* kv_ln_w = (const float*)d_in[11];
    const float* q_hw    = (const float*)d_in[12];
    const float* k_hw    = (const float*)d_in[13];
    float* out = (float*)d_out;

    // Stage 1: projections from x (tensor-core bf16-split)
    gemm_mma<<<dim3(256 / GBN, BT_ / GBM), 256>>>(x, -1, W_DQ,  nullptr, 0, BT_, 256, 512);
    gemm_mma<<<dim3(128 / GBN, BT_ / GBM), 256>>>(x, -1, W_DKV, nullptr, 1, BT_, 128, 512);
    gemm_mma<<<dim3( 64 / GBN, BT_ / GBM), 256>>>(x, -1, W_KR,  nullptr, 2, BT_,  64, 512);
    gemm_mma<<<dim3(512 / GBN, BT_ / GBM), 256>>>(x, -1, W_VR,  nullptr, 3, BT_, 512, 512);

    // Stage 2: latent RMSNorms (in place)
    rmsnorm_kernel<<<BT_, 128>>>(0, q_ln_w, 256);
    rmsnorm_kernel<<<BT_, 128>>>(1, kv_ln_w, 128);

    // Stage 3: up-projections
    gemm_mma<<<dim3(256 / GBN, BT_ / GBM), 256>>>(nullptr, 0, W_UQ, nullptr, 4, BT_, 256, 256);
    gemm_mma<<<dim3(256 / GBN, BT_ / GBM), 256>>>(nullptr, 0, W_QR, nullptr, 5, BT_, 256, 256);
    gemm_mma<<<dim3( 64 / GBN, BT_ / GBM), 256>>>(nullptr, 1, W_UK, nullptr, 6, BT_,  64, 128);
    gemm_mma<<<dim3(128 / GBN, BT_ / GBM), 256>>>(nullptr, 1, W_UV, nullptr, 7, BT_, 128, 128);

    // Stage 4: rope + head-norm + layout
    assemble_q_kernel<<<BT_, 512>>>(q_hw);
    assemble_k_kernel<<<BT_, 128>>>(k_hw);

    // Stage 5: causal flash attention + value residual
    flash_kernel<<<dim3(T_ / FBM, B_ * H_), 128>>>();

    // Stage 6: output projection -> d_out
    gemm_mma<<<dim3(512 / GBN, BT_ / GBM), 256>>>(nullptr, 10, W_O, out, -1, BT_, 512, 512);
}

// round 5
// speedup vs baseline: 2.2903x; 2.2422x over previous
#include <cuda_runtime.h>
#include <cuda_bf16.h>
#include <math.h>
#include <cstdint>

typedef __nv_bfloat16 bf16;
typedef uint32_t u32;

// Problem constants
#define B_   4
#define T_   2048
#define BT_  8192
#define H_   8
#define KVH_ 2
#define HD_  64
#define DN_  32
#define DR_  32

// ---------------------------------------------------------------------------
// Scratch buffers (device globals; no allocation allowed)
// ---------------------------------------------------------------------------
__device__ __align__(256) float g_cq  [BT_ * 256];
__device__ __align__(256) float g_ckv [BT_ * 128];
__device__ __align__(256) float g_kr  [BT_ * 64];
__device__ __align__(256) float g_vres[BT_ * 512];
__device__ __align__(256) float g_qn  [BT_ * 256];
__device__ __align__(256) float g_qr  [BT_ * 256];
__device__ __align__(256) float g_kn  [BT_ * 64];
__device__ __align__(256) float g_v   [BT_ * 128];

// bf16 hi/lo split buffers
__device__ __align__(256) bf16 g_xh   [BT_ * 512], g_xl   [BT_ * 512];
__device__ __align__(256) bf16 g_cqh  [BT_ * 256], g_cql  [BT_ * 256];
__device__ __align__(256) bf16 g_ckvh [BT_ * 128], g_ckvl [BT_ * 128];
__device__ __align__(256) bf16 g_attnh[BT_ * 512], g_attnl[BT_ * 512];
__device__ __align__(256) bf16 g_qfh  [BT_ * 512], g_qfl  [BT_ * 512];   // [B,H,T,64]
__device__ __align__(256) bf16 g_kfh  [BT_ * 128], g_kfl  [BT_ * 128];   // [B,KVH,T,64]
__device__ __align__(256) bf16 g_vth  [BT_ * 128], g_vtl  [BT_ * 128];   // [B,KVH,64,T]
__device__ __align__(256) bf16 g_wth  [909312],    g_wtl  [909312];      // transposed weights

// Transposed-weight offsets within g_wth/g_wtl
#define OFF_DQ  0
#define OFF_UQ  131072
#define OFF_QR  196608
#define OFF_DKV 262144
#define OFF_UK  327680
#define OFF_UV  335872
#define OFF_KR  352256
#define OFF_VR  385024
#define OFF_WO  647168

__device__ __forceinline__ float* bufp(int id) {
    switch (id) {
        case 0:  return g_cq;
        case 1:  return g_ckv;
        case 2:  return g_kr;
        case 3:  return g_vres;
        case 4:  return g_qn;
        case 5:  return g_qr;
        case 6:  return g_kn;
        default: return g_v;
    }
}
__device__ __forceinline__ bf16* bfh(int id) {
    switch (id) {
        case 0:  return g_xh;
        case 1:  return g_cqh;
        case 2:  return g_ckvh;
        default: return g_attnh;
    }
}
__device__ __forceinline__ bf16* bfl(int id) {
    switch (id) {
        case 0:  return g_xl;
        case 1:  return g_cql;
        case 2:  return g_ckvl;
        default: return g_attnl;
    }
}

// ---------------------------------------------------------------------------
// mma.sync bf16 (m16n8k16), fp32 accumulate, row(A) x col(B)
// ---------------------------------------------------------------------------
__device__ __forceinline__ void mma16816(float* c, const u32* a, const u32* b) {
    asm volatile(
        "mma.sync.aligned.m16n8k16.row.col.f32.bf16.bf16.f32 "
        "{%0,%1,%2,%3}, {%4,%5,%6,%7}, {%8,%9}, {%0,%1,%2,%3};"
        : "+f"(c[0]), "+f"(c[1]), "+f"(c[2]), "+f"(c[3])
        : "r"(a[0]), "r"(a[1]), "r"(a[2]), "r"(a[3]), "r"(b[0]), "r"(b[1]));
}

__device__ __forceinline__ void split2(float a, float b, u32& hi, u32& lo) {
    bf16 ha = __float2bfloat16(a), hb = __float2bfloat16(b);
    bf16 la = __float2bfloat16(a - __bfloat162float(ha));
    bf16 lb = __float2bfloat16(b - __bfloat162float(hb));
    __nv_bfloat162 Hx; Hx.x = ha; Hx.y = hb;
    __nv_bfloat162 Lx; Lx.x = la; Lx.y = lb;
    hi = *(u32*)&Hx; lo = *(u32*)&Lx;
}

// ---------------------------------------------------------------------------
// Conversion kernels
// ---------------------------------------------------------------------------
// W [K,N] fp32 -> Wt hi/lo bf16 [N,K] at offset
__global__ void __launch_bounds__(256) conv_w(const float* __restrict__ W, int K, int N, int off)
{
    int e = blockIdx.x * 256 + threadIdx.x;
    if (e >= K * N) return;
    int k = e / N, n = e - k * N;
    float v = W[e];
    bf16 h = __float2bfloat16(v);
    g_wth[off + n * K + k] = h;
    g_wtl[off + n * K + k] = __float2bfloat16(v - __bfloat162float(h));
}

// x fp32 -> hi/lo bf16 (same layout)
__global__ void __launch_bounds__(256) conv_x(const float* __restrict__ x)
{
    int e = blockIdx.x * 256 + threadIdx.x;
    float v = x[e];
    bf16 h = __float2bfloat16(v);
    g_xh[e] = h;
    g_xl[e] = __float2bfloat16(v - __bfloat162float(h));
}

// g_v fp32 [B,T,KVH*64] -> V^T hi/lo [B,KVH,64,T] (smem tile transpose)
__global__ void __launch_bounds__(256) vtrans_kernel()
{
    __shared__ float ts[64][65];
    int tt  = blockIdx.x * 64;              // token tile
    int bk  = blockIdx.y;                   // b*KVH + kvh
    int b   = bk >> 1, kvh = bk & 1;
    int tid = threadIdx.x;

#pragma unroll
    for (int i = 0; i < 16; i++) {
        int e = tid + i * 256;
        int t = e >> 6, d = e & 63;
        ts[d][t] = g_v[((size_t)(b * T_) + tt + t) * 128 + kvh * 64 + d];
    }
    __syncthreads();
#pragma unroll
    for (int i = 0; i < 16; i++) {
        int e = tid + i * 256;
        int d = e >> 6, t = e & 63;
        float v = ts[d][t];
        bf16 h = __float2bfloat16(v);
        size_t o = ((size_t)bk * 64 + d) * T_ + tt + t;
        g_vth[o] = h;
        g_vtl[o] = __float2bfloat16(v - __bfloat162float(h));
    }
}

// ---------------------------------------------------------------------------
// GEMM: C[M,N] fp32 = A @ W, A from bf16 hi/lo pair (id), W from g_wth/l [N][K].
// Block 128x64, BK=32, 256 threads (8 warps 4x2, warp tile 32x32), 3-term split.
// ---------------------------------------------------------------------------
#define GBM 128
#define GBN 64
#define GBK 32
#define ASTR 36

__global__ void __launch_bounds__(256) gemm_bf(
    int Aid, int Woff, float* Cp, int Cid, int M, int N, int K)
{
    const bf16* Ahg = bfh(Aid);
    const bf16* Alg = bfl(Aid);
    const bf16* Bhg = g_wth + Woff;
    const bf16* Blg = g_wtl + Woff;
    float* C = (Cid >= 0) ? bufp(Cid) : Cp;

    __shared__ bf16 Ah[GBM][ASTR], Al[GBM][ASTR];
    __shared__ bf16 Bh[GBN][ASTR], Bl[GBN][ASTR];

    const int bm   = blockIdx.y * GBM;
    const int bn   = blockIdx.x * GBN;
    const int tid  = threadIdx.x;
    const int warp = tid >> 5;
    const int lane = tid & 31;
    const int wm   = (warp & 3) * 32;
    const int wn   = (warp >> 2) * 32;
    const int grp  = lane >> 2;
    const int tig  = lane & 3;

    float acc[2][4][4];
#pragma unroll
    for (int mi = 0; mi < 2; mi++)
#pragma unroll
        for (int ni = 0; ni < 4; ni++)
#pragma unroll
            for (int i = 0; i < 4; i++) acc[mi][ni][i] = 0.f;

    for (int k0 = 0; k0 < K; k0 += GBK) {
        // A tiles: 128 x 32 bf16, u32 copies (16 u32/row)
#pragma unroll
        for (int i = 0; i < 8; i++) {
            int e = tid + i * 256;
            int r = e >> 4, c2 = (e & 15) * 2;
            *(u32*)&Ah[r][c2] = *(const u32*)&Ahg[(size_t)(bm + r) * K + k0 + c2];
            *(u32*)&Al[r][c2] = *(const u32*)&Alg[(size_t)(bm + r) * K + k0 + c2];
        }
        // B tiles: 64 x 32 bf16 (Wt rows)
#pragma unroll
        for (int i = 0; i < 4; i++) {
            int e = tid + i * 256;
            int r = e >> 4, c2 = (e & 15) * 2;
            *(u32*)&Bh[r][c2] = *(const u32*)&Bhg[(size_t)(bn + r) * K + k0 + c2];
            *(u32*)&Bl[r][c2] = *(const u32*)&Blg[(size_t)(bn + r) * K + k0 + c2];
        }
        __syncthreads();

#pragma unroll
        for (int ks = 0; ks < GBK; ks += 16) {
            u32 ah[2][4], al[2][4], bh[4][2], bl[4][2];
#pragma unroll
            for (int mi = 0; mi < 2; mi++) {
                int r0 = wm + mi * 16 + grp;
                int c0 = ks + tig * 2;
                ah[mi][0] = *(const u32*)&Ah[r0][c0];
                ah[mi][1] = *(const u32*)&Ah[r0 + 8][c0];
                ah[mi][2] = *(const u32*)&Ah[r0][c0 + 8];
                ah[mi][3] = *(const u32*)&Ah[r0 + 8][c0 + 8];
                al[mi][0] = *(const u32*)&Al[r0][c0];
                al[mi][1] = *(const u32*)&Al[r0 + 8][c0];
                al[mi][2] = *(const u32*)&Al[r0][c0 + 8];
                al[mi][3] = *(const u32*)&Al[r0 + 8][c0 + 8];
            }
#pragma unroll
            for (int ni = 0; ni < 4; ni++) {
                int n0 = wn + ni * 8 + grp;
                int c0 = ks + tig * 2;
                bh[ni][0] = *(const u32*)&Bh[n0][c0];
                bh[ni][1] = *(const u32*)&Bh[n0][c0 + 8];
                bl[ni][0] = *(const u32*)&Bl[n0][c0];
                bl[ni][1] = *(const u32*)&Bl[n0][c0 + 8];
            }
#pragma unroll
            for (int mi = 0; mi < 2; mi++)
#pragma unroll
                for (int ni = 0; ni < 4; ni++) {
                    mma16816(acc[mi][ni], ah[mi], bh[ni]);
                    mma16816(acc[mi][ni], ah[mi], bl[ni]);
                    mma16816(acc[mi][ni], al[mi], bh[ni]);
                }
        }
        __syncthreads();
    }

#pragma unroll
    for (int mi = 0; mi < 2; mi++) {
#pragma unroll
        for (int ni = 0; ni < 4; ni++) {
            int row = bm + wm + mi * 16 + grp;
            int col = bn + wn + ni * 8 + tig * 2;
            *(float2*)&C[(size_t)row * N + col]       = make_float2(acc[mi][ni][0], acc[mi][ni][1]);
            *(float2*)&C[(size_t)(row + 8) * N + col] = make_float2(acc[mi][ni][2], acc[mi][ni][3]);
        }
    }
}

// ---------------------------------------------------------------------------
// RMSNorm: fp32 src (bufp id) -> bf16 hi/lo dst (bfh/bfl id), one block per row
// ---------------------------------------------------------------------------
__global__ void __launch_bounds__(128) rmsnorm_kernel(int srcid, int dstid,
                                                      const float* __restrict__ w, int N)
{
    const float* x = bufp(srcid) + (size_t)blockIdx.x * N;
    bf16* dh = bfh(dstid) + (size_t)blockIdx.x * N;
    bf16* dl = bfl(dstid) + (size_t)blockIdx.x * N;
    int tid = threadIdx.x;

    float ss = 0.f;
    for (int i = tid; i < N; i += 128) { float v = x[i]; ss = fmaf(v, v, ss); }
#pragma unroll
    for (int o = 16; o; o >>= 1) ss += __shfl_xor_sync(0xffffffffu, ss, o);

    __shared__ float sp[4];
    if ((tid & 31) == 0) sp[tid >> 5] = ss;
    __syncthreads();
    float tot = sp[0] + sp[1] + sp[2] + sp[3];
    float sc = rsqrtf(tot / (float)N + 1e-6f);

    for (int i = tid; i < N; i += 128) {
        float v = x[i] * sc * w[i];
        bf16 h = __float2bfloat16(v);
        dh[i] = h;
        dl[i] = __float2bfloat16(v - __bfloat162float(h));
    }
}

// ---------------------------------------------------------------------------
// Rope helper
// ---------------------------------------------------------------------------
__device__ __forceinline__ void rope_cs(int t, int dr, float& c, float& s)
{
    int j = dr & 15;
    float inv = 1.0f / powf(500000.0f, (float)(2 * j) * (1.0f / 32.0f));
    float ang = (float)t * inv;
    sincosf(ang, &s, &c);
}

// ---------------------------------------------------------------------------
// Assemble Q -> per-head RMSNorm -> g_qfh/l [B,H,T,64] bf16
// ---------------------------------------------------------------------------
__global__ void __launch_bounds__(512) assemble_q_kernel(const float* __restrict__ hw)
{
    int token = blockIdx.x;
    int b = token >> 11;
    int t = token & 2047;
    int tid = threadIdx.x;
    int h = tid >> 6;
    int d = tid & 63;

    const float* qn = g_qn + (size_t)token * 256 + h * 32;
    const float* qr = g_qr + (size_t)token * 256 + h * 32;

    float val;
    if (d < DN_) {
        val = qn[d];
    } else {
        int dr = d - DN_;
        float c, s;
        rope_cs(t, dr, c, s);
        val = (dr < 16) ? (qr[dr] * c - qr[dr + 16] * s)
                        : (qr[dr] * c + qr[dr - 16] * s);
    }

    float ss = val * val;
#pragma unroll
    for (int o = 16; o; o >>= 1) ss += __shfl_xor_sync(0xffffffffu, ss, o);
    __shared__ float sp[16];
    if ((tid & 31) == 0) sp[tid >> 5] = ss;
    __syncthreads();
    float tot = sp[2 * h] + sp[2 * h + 1];
    float sc = rsqrtf(tot * (1.0f / 64.0f) + 1e-6f);

    float out = val * sc * hw[d];
    size_t o = ((size_t)(b * H_ + h) * T_ + t) * HD_ + d;
    bf16 hh = __float2bfloat16(out);
    g_qfh[o] = hh;
    g_qfl[o] = __float2bfloat16(out - __bfloat162float(hh));
}

// ---------------------------------------------------------------------------
// Assemble K -> g_kfh/l [B,KVH,T,64] bf16
// ---------------------------------------------------------------------------
__global__ void __launch_bounds__(128) assemble_k_kernel(const float* __restrict__ hw)
{
    int token = blockIdx.x;
    int b = token >> 11;
    int t = token & 2047;
    int tid = threadIdx.x;
    int h = tid >> 6;
    int d = tid & 63;

    const float* kn = g_kn + (size_t)token * 64 + h * 32;
    const float* kr = g_kr + (size_t)token * 64 + h * 32;

    float val;
    if (d < DN_) {
        val = kn[d];
    } else {
        int dr = d - DN_;
        float c, s;
        rope_cs(t, dr, c, s);
        val = (dr < 16) ? (kr[dr] * c - kr[dr + 16] * s)
                        : (kr[dr] * c + kr[dr - 16] * s);
    }

    float ss = val * val;
#pragma unroll
    for (int o = 16; o; o >>= 1) ss += __shfl_xor_sync(0xffffffffu, ss, o);
    __shared__ float sp[4];
    if ((tid & 31) == 0) sp[tid >> 5] = ss;
    __syncthreads();
    float tot = sp[2 * h] + sp[2 * h + 1];
    float sc = rsqrtf(tot * (1.0f / 64.0f) + 1e-6f);

    float out = val * sc * hw[d];
    size_t o = ((size_t)(b * KVH_ + h) * T_ + t) * HD_ + d;
    bf16 hh = __float2bfloat16(out);
    g_kfh[o] = hh;
    g_kfl[o] = __float2bfloat16(out - __bfloat162float(hh));
}

// ---------------------------------------------------------------------------
// Flash attention on mma.sync (bf16 split), causal, GQA, fused v_res.
// grid (T/128, B*H), 256 threads (8 warps x 16 q-rows). BN=64 keys.
// Writes g_attnh/l bf16 [B*T, 512].
// ---------------------------------------------------------------------------
#define FSC 0.125f

__global__ void __launch_bounds__(256) flash_mma()
{
    __shared__ bf16 Kh_s[64][72], Kl_s[64][72];
    __shared__ bf16 Vh_s[64][72], Vl_s[64][72];

    const int bh   = blockIdx.y;
    const int b    = bh >> 3;
    const int h    = bh & 7;
    const int kvh  = h >> 2;
    const int qs   = blockIdx.x * 128;
    const int tid  = threadIdx.x;
    const int warp = tid >> 5;
    const int lane = tid & 31;
    const int grp  = lane >> 2;
    const int tig  = lane & 3;
    const int wm   = warp * 16;

    const bf16* qhb = g_qfh + ((size_t)(b * H_ + h) * T_) * 64;
    const bf16* qlb = g_qfl + ((size_t)(b * H_ + h) * T_) * 64;
    const bf16* khb = g_kfh + ((size_t)(b * KVH_ + kvh) * T_) * 64;
    const bf16* klb = g_kfl + ((size_t)(b * KVH_ + kvh) * T_) * 64;
    const bf16* vhb = g_vth + ((size_t)(b * KVH_ + kvh) * 64) * T_;
    const bf16* vlb = g_vtl + ((size_t)(b * KVH_ + kvh) * 64) * T_;

    const int q0 = qs + wm + grp;
    const int q1 = q0 + 8;

    // Q fragments (held in registers for the whole K loop)
    u32 qfh[4][4], qfl[4][4];
#pragma unroll
    for (int kst = 0; kst < 4; kst++) {
        int c0 = kst * 16 + tig * 2;
        qfh[kst][0] = *(const u32*)&qhb[(size_t)q0 * 64 + c0];
        qfh[kst][1] = *(const u32*)&qhb[(size_t)q1 * 64 + c0];
        qfh[kst][2] = *(const u32*)&qhb[(size_t)q0 * 64 + c0 + 8];
        qfh[kst][3] = *(const u32*)&qhb[(size_t)q1 * 64 + c0 + 8];
        qfl[kst][0] = *(const u32*)&qlb[(size_t)q0 * 64 + c0];
        qfl[kst][1] = *(const u32*)&qlb[(size_t)q1 * 64 + c0];
        qfl[kst][2] = *(const u32*)&qlb[(size_t)q0 * 64 + c0 + 8];
        qfl[kst][3] = *(const u32*)&qlb[(size_t)q1 * 64 + c0 + 8];
    }

    float oa[8][4];
#pragma unroll
    for (int n = 0; n < 8; n++)
#pragma unroll
        for (int i = 0; i < 4; i++) oa[n][i] = 0.f;
    float m0 = -1e30f, m1 = -1e30f, l0 = 0.f, l1 = 0.f;

    const int kend = qs + 128;
    for (int ks = 0; ks < kend; ks += 64) {
        // Stage K and V^T tiles (hi/lo)
#pragma unroll
        for (int i = 0; i < 8; i++) {
            int e = tid + i * 256;
            int r = e >> 5, c2 = (e & 31) * 2;
            *(u32*)&Kh_s[r][c2] = *(const u32*)&khb[(size_t)(ks + r) * 64 + c2];
            *(u32*)&Kl_s[r][c2] = *(const u32*)&klb[(size_t)(ks + r) * 64 + c2];
            *(u32*)&Vh_s[r][c2] = *(const u32*)&vhb[(size_t)r * T_ + ks + c2];
            *(u32*)&Vl_s[r][c2] = *(const u32*)&vlb[(size_t)r * T_ + ks + c2];
        }
        __syncthreads();

        if (ks <= qs + wm + 15) {       // warp has at least one valid key
            // S = Q K^T (3-term split)
            float sa[8][4];
#pragma unroll
            for (int n = 0; n < 8; n++)
#pragma unroll
                for (int i = 0; i < 4; i++) sa[n][i] = 0.f;

#pragma unroll
            for (int kst = 0; kst < 4; kst++) {
                int c0 = kst * 16 + tig * 2;
#pragma unroll
                for (int n = 0; n < 8; n++) {
                    int r = n * 8 + grp;
                    u32 bh[2], bl[2];
                    bh[0] = *(const u32*)&Kh_s[r][c0];
                    bh[1] = *(const u32*)&Kh_s[r][c0 + 8];
                    bl[0] = *(const u32*)&Kl_s[r][c0];
                    bl[1] = *(const u32*)&Kl_s[r][c0 + 8];
                    mma16816(sa[n], qfh[kst], bh);
                    mma16816(sa[n], qfh[kst], bl);
                    mma16816(sa[n], qfl[kst], bh);
                }
            }

            // Mask + scale + row max
            float mx0 = m0, mx1 = m1;
#pragma unroll
            for (int n = 0; n < 8; n++) {
                int kb = ks + n * 8 + tig * 2;
                float v0 = (kb     <= q0) ? sa[n][0] * FSC : -1e30f;
                float v1 = (kb + 1 <= q0) ? sa[n][1] * FSC : -1e30f;
                float v2 = (kb     <= q1) ? sa[n][2] * FSC : -1e30f;
                float v3 = (kb + 1 <= q1) ? sa[n][3] * FSC : -1e30f;
                sa[n][0] = v0; sa[n][1] = v1; sa[n][2] = v2; sa[n][3] = v3;
                mx0 = fmaxf(mx0, fmaxf(v0, v1));
                mx1 = fmaxf(mx1, fmaxf(v2, v3));
            }
            mx0 = fmaxf(mx0, __shfl_xor_sync(0xffffffffu, mx0, 1));
            mx0 = fmaxf(mx0, __shfl_xor_sync(0xffffffffu, mx0, 2));
            mx1 = fmaxf(mx1, __shfl_xor_sync(0xffffffffu, mx1, 1));
            mx1 = fmaxf(mx1, __shfl_xor_sync(0xffffffffu, mx1, 2));

            float corr0 = __expf(m0 - mx0);
            float corr1 = __expf(m1 - mx1);
            m0 = mx0; m1 = mx1;
            l0 *= corr0; l1 *= corr1;
#pragma unroll
            for (int n = 0; n < 8; n++) {
                oa[n][0] *= corr0; oa[n][1] *= corr0;
                oa[n][2] *= corr1; oa[n][3] *= corr1;
            }

            // P = exp(S - m), accumulate l (thread-partial; quad-reduced at end)
            float ls0 = 0.f, ls1 = 0.f;
#pragma unroll
            for (int n = 0; n < 8; n++) {
                float p0 = __expf(sa[n][0] - mx0);
                float p1 = __expf(sa[n][1] - mx0);
                float p2 = __expf(sa[n][2] - mx1);
                float p3 = __expf(sa[n][3] - mx1);
                sa[n][0] = p0; sa[n][1] = p1; sa[n][2] = p2; sa[n][3] = p3;
                ls0 += p0 + p1; ls1 += p2 + p3;
            }
            l0 += ls0; l1 += ls1;

            // PV (3-term split); P frags built directly from sa registers
#pragma unroll
            for (int kt = 0; kt < 4; kt++) {
                u32 ah[4], al[4];
                split2(sa[2 * kt][0],     sa[2 * kt][1],     ah[0], al[0]);
                split2(sa[2 * kt][2],     sa[2 * kt][3],     ah[1], al[1]);
                split2(sa[2 * kt + 1][0], sa[2 * kt + 1][1], ah[2], al[2]);
                split2(sa[2 * kt + 1][2], sa[2 * kt + 1][3], ah[3], al[3]);
                int c0 = kt * 16 + tig * 2;
#pragma unroll
                for (int n = 0; n < 8; n++) {
                    int r = n * 8 + grp;
                    u32 bh[2], bl[2];
                    bh[0] = *(const u32*)&Vh_s[r][c0];
                    bh[1] = *(const u32*)&Vh_s[r][c0 + 8];
                    bl[0] = *(const u32*)&Vl_s[r][c0];
                    bl[1] = *(const u32*)&Vl_s[r][c0 + 8];
                    mma16816(oa[n], ah, bh);
                    mma16816(oa[n], ah, bl);
                    mma16816(oa[n], al, bh);
                }
            }
        }
        __syncthreads();
    }

    // FIX (R5): l0/l1 are per-thread partial sums over this thread's key
    // columns; the full row sum lives across the 4 threads of the lane quad.
    // All quad threads share the same m trajectory, so partials are
    // consistently scaled and a plain quad reduction is exact.
    l0 += __shfl_xor_sync(0xffffffffu, l0, 1);
    l0 += __shfl_xor_sync(0xffffffffu, l0, 2);
    l1 += __shfl_xor_sync(0xffffffffu, l1, 1);
    l1 += __shfl_xor_sync(0xffffffffu, l1, 2);

    // Epilogue: normalize, add v_res, write attn hi/lo bf16
    float inv0 = 1.0f / l0;
    float inv1 = 1.0f / l1;
    size_t row0 = (size_t)b * T_ + q0;
    size_t row1 = (size_t)b * T_ + q1;
#pragma unroll
    for (int n = 0; n < 8; n++) {
        int col = h * 64 + n * 8 + tig * 2;
        float a0 = oa[n][0] * inv0 + g_vres[row0 * 512 + col];
        float a1 = oa[n][1] * inv0 + g_vres[row0 * 512 + col + 1];
        float a2 = oa[n][2] * inv1 + g_vres[row1 * 512 + col];
        float a3 = oa[n][3] * inv1 + g_vres[row1 * 512 + col + 1];
        u32 h01, l01, h23, l23;
        split2(a0, a1, h01, l01);
        split2(a2, a3, h23, l23);
        *(u32*)&g_attnh[row0 * 512 + col] = h01;
        *(u32*)&g_attnl[row0 * 512 + col] = l01;
        *(u32*)&g_attnh[row1 * 512 + col] = h23;
        *(u32*)&g_attnl[row1 * 512 + col] = l23;
    }
}

// ---------------------------------------------------------------------------
// Launch
// ---------------------------------------------------------------------------
extern "C" void kernel_launch(void* const* d_in, const int* in_sizes, int n_in,
                              void* d_out, int out_size)
{
    const float* x       = (const float*)d_in[0];
    const float* W_DQ    = (const float*)d_in[1];
    const float* W_UQ    = (const float*)d_in[2];
    const float* W_QR    = (const float*)d_in[3];
    const float* W_DKV   = (const float*)d_in[4];
    const float* W_UK    = (const float*)d_in[5];
    const float* W_UV    = (const float*)d_in[6];
    const float* W_KR    = (const float*)d_in[7];
    const float* W_VR    = (const float*)d_in[8];
    const float* W_O     = (const float*)d_in[9];
    const float* q_ln_w  = (const float*)d_in[10];
    const float* kv_ln_w = (const float*)d_in[11];
    const float* q_hw    = (const float*)d_in[12];
    const float* k_hw    = (const float*)d_in[13];
    float* out = (float*)d_out;

    // Stage 0: one-time splits (weights transposed)
    conv_w<<<(512 * 256 + 255) / 256, 256>>>(W_DQ,  512, 256, OFF_DQ);
    conv_w<<<(256 * 256 + 255) / 256, 256>>>(W_UQ,  256, 256, OFF_UQ);
    conv_w<<<(256 * 256 + 255) / 256, 256>>>(W_QR,  256, 256, OFF_QR);
    conv_w<<<(512 * 128 + 255) / 256, 256>>>(W_DKV, 512, 128, OFF_DKV);
    conv_w<<<(128 * 64  + 255) / 256, 256>>>(W_UK,  128,  64, OFF_UK);
    conv_w<<<(128 * 128 + 255) / 256, 256>>>(W_UV,  128, 128, OFF_UV);
    conv_w<<<(512 * 64  + 255) / 256, 256>>>(W_KR,  512,  64, OFF_KR);
    conv_w<<<(512 * 512 + 255) / 256, 256>>>(W_VR,  512, 512, OFF_VR);
    conv_w<<<(512 * 512 + 255) / 256, 256>>>(W_O,   512, 512, OFF_WO);
    conv_x<<<(BT_ * 512) / 256, 256>>>(x);

    // Stage 1: down projections
    gemm_bf<<<dim3(4, 64), 256>>>(0, OFF_DQ,  nullptr, 0, BT_, 256, 512);
    gemm_bf<<<dim3(2, 64), 256>>>(0, OFF_DKV, nullptr, 1, BT_, 128, 512);
    gemm_bf<<<dim3(1, 64), 256>>>(0, OFF_KR,  nullptr, 2, BT_,  64, 512);
    gemm_bf<<<dim3(8, 64), 256>>>(0, OFF_VR,  nullptr, 3, BT_, 512, 512);

    // Stage 2: latent RMSNorms (fp32 -> bf16 hi/lo)
    rmsnorm_kernel<<<BT_, 128>>>(0, 1, q_ln_w, 256);
    rmsnorm_kernel<<<BT_, 128>>>(1, 2, kv_ln_w, 128);

    // Stage 3: up projections
    gemm_bf<<<dim3(4, 64), 256>>>(1, OFF_UQ, nullptr, 4, BT_, 256, 256);
    gemm_bf<<<dim3(4, 64), 256>>>(1, OFF_QR, nullptr, 5, BT_, 256, 256);
    gemm_bf<<<dim3(1, 64), 256>>>(2, OFF_UK, nullptr, 6, BT_,  64, 128);
    gemm_bf<<<dim3(2, 64), 256>>>(2, OFF_UV, nullptr, 7, BT_, 128, 128);

    // Stage 4: rope + head-norm + layout; V transpose
    assemble_q_kernel<<<BT_, 512>>>(q_hw);
    assemble_k_kernel<<<BT_, 128>>>(k_hw);
    vtrans_kernel<<<dim3(T_ / 64, B_ * KVH_), 256>>>();

    // Stage 5: flash attention (tensor cores) + v_res
    flash_mma<<<dim3(T_ / 128, B_ * H_), 256>>>();

    // Stage 6: output projection -> d_out
    gemm_bf<<<dim3(8, 64), 256>>>(3, OFF_WO, out, -1, BT_, 512, 512);
}

// round 6
// speedup vs baseline: 2.9960x; 1.3081x over previous
#include <cuda_runtime.h>
#include <cuda_bf16.h>
#include <math.h>
#include <cstdint>

typedef __nv_bfloat16 bf16;
typedef uint32_t u32;

// Problem constants
#define B_   4
#define T_   2048
#define BT_  8192
#define H_   8
#define KVH_ 2
#define HD_  64
#define DN_  32
#define DR_  32

// ---------------------------------------------------------------------------
// Scratch buffers (device globals; no allocation allowed)
// ---------------------------------------------------------------------------
// Stage-1 combined output: [cq(256) | ckv(128) | kr(64) | vres(512)] per token
__device__ __align__(256) float g_s1 [BT_ * 960];
// Stage-3a combined: [q_nope(256) | q_rope(256)]
__device__ __align__(256) float g_qnr[BT_ * 512];
// Stage-3b combined: [k_nope(64) | v(128)]
__device__ __align__(256) float g_kv [BT_ * 192];

// bf16 hi/lo split buffers
__device__ __align__(256) bf16 g_xh   [BT_ * 512], g_xl   [BT_ * 512];
__device__ __align__(256) bf16 g_cqh  [BT_ * 256], g_cql  [BT_ * 256];
__device__ __align__(256) bf16 g_ckvh [BT_ * 128], g_ckvl [BT_ * 128];
__device__ __align__(256) bf16 g_attnh[BT_ * 512], g_attnl[BT_ * 512];
__device__ __align__(256) bf16 g_qfh  [BT_ * 512], g_qfl  [BT_ * 512];   // [B,H,T,64]
__device__ __align__(256) bf16 g_kfh  [BT_ * 128], g_kfl  [BT_ * 128];   // [B,KVH,T,64]
__device__ __align__(256) bf16 g_vth  [BT_ * 128], g_vtl  [BT_ * 128];   // [B,KVH,64,T]
__device__ __align__(256) bf16 g_wth  [909312],    g_wtl  [909312];      // transposed weights

// rope tables [T][16]
__device__ __align__(256) float g_ropec[T_ * 16], g_ropes[T_ * 16];

// Transposed-weight offsets (row-major [N][K] regions)
// W1 (K=512): rows 0-255 DQ | 256-383 DKV | 384-447 KR | 448-959 VR
#define OFF_DQ   0
#define OFF_DKV  131072     // 256*512
#define OFF_KR   196608     // 384*512
#define OFF_VR   229376     // 448*512
// W2 (K=256): rows 0-255 UQ | 256-511 QR
#define OFF_W2   491520     // 960*512
#define OFF_UQ   491520
#define OFF_QR   557056     // OFF_W2 + 256*256
// W3 (K=128): rows 0-63 UK | 64-191 UV
#define OFF_W3   622592     // OFF_W2 + 512*256
#define OFF_UK   622592
#define OFF_UV   630784     // OFF_W3 + 64*128
// WO (K=512): 512 rows
#define OFF_WO   647168     // OFF_W3 + 192*128

__device__ __forceinline__ bf16* bfh(int id) {
    switch (id) {
        case 0:  return g_xh;
        case 1:  return g_cqh;
        case 2:  return g_ckvh;
        default: return g_attnh;
    }
}
__device__ __forceinline__ bf16* bfl(int id) {
    switch (id) {
        case 0:  return g_xl;
        case 1:  return g_cql;
        case 2:  return g_ckvl;
        default: return g_attnl;
    }
}

// ---------------------------------------------------------------------------
// mma.sync bf16 (m16n8k16), fp32 accumulate, row(A) x col(B)
// ---------------------------------------------------------------------------
__device__ __forceinline__ void mma16816(float* c, const u32* a, const u32* b) {
    asm volatile(
        "mma.sync.aligned.m16n8k16.row.col.f32.bf16.bf16.f32 "
        "{%0,%1,%2,%3}, {%4,%5,%6,%7}, {%8,%9}, {%0,%1,%2,%3};"
        : "+f"(c[0]), "+f"(c[1]), "+f"(c[2]), "+f"(c[3])
        : "r"(a[0]), "r"(a[1]), "r"(a[2]), "r"(a[3]), "r"(b[0]), "r"(b[1]));
}

__device__ __forceinline__ void split2(float a, float b, u32& hi, u32& lo) {
    bf16 ha = __float2bfloat16(a), hb = __float2bfloat16(b);
    bf16 la = __float2bfloat16(a - __bfloat162float(ha));
    bf16 lb = __float2bfloat16(b - __bfloat162float(hb));
    __nv_bfloat162 Hx; Hx.x = ha; Hx.y = hb;
    __nv_bfloat162 Lx; Lx.x = la; Lx.y = lb;
    hi = *(u32*)&Hx; lo = *(u32*)&Lx;
}

// cp.async helpers (base ISA, sm_80+)
__device__ __forceinline__ void cpa16(u32 dst, const void* src) {
    asm volatile("cp.async.cg.shared.global [%0], [%1], 16;" :: "r"(dst), "l"(src) : "memory");
}
#define CP_COMMIT() asm volatile("cp.async.commit_group;" ::: "memory")
#define CP_WAIT1()  asm volatile("cp.async.wait_group 1;" ::: "memory")
#define CP_WAIT0()  asm volatile("cp.async.wait_group 0;" ::: "memory")

// ---------------------------------------------------------------------------
// Conversion kernels
// ---------------------------------------------------------------------------
__device__ __forceinline__ void conv_one(const float* __restrict__ W,
                                         int K, int N, int off, int e)
{
    int k = e / N, n = e - k * N;
    float v = W[e];
    bf16 h = __float2bfloat16(v);
    g_wth[off + n * K + k] = h;
    g_wtl[off + n * K + k] = __float2bfloat16(v - __bfloat162float(h));
}

// All 9 weights in one launch; block ranges (elem counts all multiples of 256).
__global__ void __launch_bounds__(256) conv_all(
    const float* W_DQ, const float* W_UQ, const float* W_QR,
    const float* W_DKV, const float* W_UK, const float* W_UV,
    const float* W_KR, const float* W_VR, const float* W_O)
{
    int blk = blockIdx.x;
    int tid = threadIdx.x;
    if      (blk < 512)  conv_one(W_DQ,  512, 256, OFF_DQ,  (blk)        * 256 + tid);
    else if (blk < 768)  conv_one(W_UQ,  256, 256, OFF_UQ,  (blk - 512)  * 256 + tid);
    else if (blk < 1024) conv_one(W_QR,  256, 256, OFF_QR,  (blk - 768)  * 256 + tid);
    else if (blk < 1280) conv_one(W_DKV, 512, 128, OFF_DKV, (blk - 1024) * 256 + tid);
    else if (blk < 1312) conv_one(W_UK,  128,  64, OFF_UK,  (blk - 1280) * 256 + tid);
    else if (blk < 1376) conv_one(W_UV,  128, 128, OFF_UV,  (blk - 1312) * 256 + tid);
    else if (blk < 1504) conv_one(W_KR,  512,  64, OFF_KR,  (blk - 1376) * 256 + tid);
    else if (blk < 2528) conv_one(W_VR,  512, 512, OFF_VR,  (blk - 1504) * 256 + tid);
    else                 conv_one(W_O,   512, 512, OFF_WO,  (blk - 2528) * 256 + tid);
}

__global__ void __launch_bounds__(256) conv_x(const float* __restrict__ x)
{
    int e = blockIdx.x * 256 + threadIdx.x;
    float v = x[e];
    bf16 h = __float2bfloat16(v);
    g_xh[e] = h;
    g_xl[e] = __float2bfloat16(v - __bfloat162float(h));
}

__global__ void __launch_bounds__(256) rope_tab()
{
    int e = blockIdx.x * 256 + threadIdx.x;   // 32768 entries
    int t = e >> 4, j = e & 15;
    float inv = powf(500000.0f, -(float)j / 16.0f);
    float s, c;
    sincosf((float)t * inv, &s, &c);
    g_ropec[e] = c;
    g_ropes[e] = s;
}

// g_kv fp32 [BT,192] (v at cols 64..191) -> V^T hi/lo [B,KVH,64,T]
__global__ void __launch_bounds__(256) vtrans_kernel()
{
    __shared__ float ts[64][65];
    int tt  = blockIdx.x * 64;
    int bk  = blockIdx.y;                   // b*KVH + kvh
    int b   = bk >> 1, kvh = bk & 1;
    int tid = threadIdx.x;

#pragma unroll
    for (int i = 0; i < 16; i++) {
        int e = tid + i * 256;
        int t = e >> 6, d = e & 63;
        ts[d][t] = g_kv[((size_t)(b * T_) + tt + t) * 192 + 64 + kvh * 64 + d];
    }
    __syncthreads();
#pragma unroll
    for (int i = 0; i < 16; i++) {
        int e = tid + i * 256;
        int d = e >> 6, t = e & 63;
        float v = ts[d][t];
        bf16 h = __float2bfloat16(v);
        size_t o = ((size_t)bk * 64 + d) * T_ + tt + t;
        g_vth[o] = h;
        g_vtl[o] = __float2bfloat16(v - __bfloat162float(h));
    }
}

// ---------------------------------------------------------------------------
// GEMM: C[M,N] fp32 = A @ W. A = bf16 hi/lo (Aid), W = g_wth/l rows [N][K].
// Block 128x64, BK=32, 256 threads (8 warps 4x2), 3-term bf16 split.
// cp.async double-buffered; XOR-swizzled smem (16B chunks in 64B rows).
// ---------------------------------------------------------------------------
#define STG_BYTES 24576   // per stage: Ah 8K | Al 8K | Bh 4K | Bl 4K

__device__ __forceinline__ u32 sw_off(int r, int cb) {
    return (u32)(r * 64 + (((cb >> 4) ^ ((r >> 1) & 3)) << 4) + (cb & 15));
}

__global__ void __launch_bounds__(256) gemm_bf(
    int Aid, int Woff, float* Cp, int Cid, int M, int N, int K)
{
    const bf16* __restrict__ Ahg = bfh(Aid);
    const bf16* __restrict__ Alg = bfl(Aid);
    const bf16* __restrict__ Bhg = g_wth + Woff;
    const bf16* __restrict__ Blg = g_wtl + Woff;
    float* C;
    switch (Cid) { case 0: C = g_s1; break; case 1: C = g_qnr; break;
                   case 2: C = g_kv; break; default: C = Cp; }

    __shared__ __align__(16) unsigned char sm[2][STG_BYTES];
    const u32 smbase = (u32)__cvta_generic_to_shared(&sm[0][0]);

    const int bm   = blockIdx.y * 128;
    const int bn   = blockIdx.x * 64;
    const int tid  = threadIdx.x;
    const int warp = tid >> 5;
    const int lane = tid & 31;
    const int wm   = (warp & 3) * 32;
    const int wn   = (warp >> 2) * 32;
    const int grp  = lane >> 2;
    const int tig  = lane & 3;

    float acc[2][4][4];
#pragma unroll
    for (int mi = 0; mi < 2; mi++)
#pragma unroll
        for (int ni = 0; ni < 4; ni++)
#pragma unroll
            for (int i = 0; i < 4; i++) acc[mi][ni][i] = 0.f;

    // async stage loader: 1536 x 16B ops, 6 per thread
    auto load_stage = [&](int s, int k0) {
#pragma unroll
        for (int i = 0; i < 6; i++) {
            int e = tid + i * 256;
            const bf16* src;
            u32 dst;
            if (e < 1024) {
                int hl = e >> 9, idx = e & 511;
                int r = idx >> 2, c16 = idx & 3;
                src = (hl ? Alg : Ahg) + (size_t)(bm + r) * K + k0 + c16 * 8;
                dst = smbase + s * STG_BYTES + hl * 8192 + r * 64
                    + ((c16 ^ ((r >> 1) & 3)) << 4);
            } else {
                int idx = e - 1024;
                int hl = idx >> 8; idx &= 255;
                int r = idx >> 2, c16 = idx & 3;
                src = (hl ? Blg : Bhg) + (size_t)(bn + r) * K + k0 + c16 * 8;
                dst = smbase + s * STG_BYTES + 16384 + hl * 4096 + r * 64
                    + ((c16 ^ ((r >> 1) & 3)) << 4);
            }
            cpa16(dst, src);
        }
    };

    const int nch = K / 32;
    load_stage(0, 0);
    CP_COMMIT();

    for (int kc = 0; kc < nch; kc++) {
        if (kc + 1 < nch) {
            load_stage((kc + 1) & 1, (kc + 1) * 32);
            CP_COMMIT();
            CP_WAIT1();
        } else {
            CP_WAIT0();
        }
        __syncthreads();

        const unsigned char* st = sm[kc & 1];
#pragma unroll
        for (int ks = 0; ks < 2; ks++) {
            int cb = ks * 32 + tig * 4;            // byte col of frag base
            u32 ah[2][4], al[2][4], bhf[4][2], blf[4][2];
#pragma unroll
            for (int mi = 0; mi < 2; mi++) {
                int r0 = wm + mi * 16 + grp;
                ah[mi][0] = *(const u32*)(st + sw_off(r0,     cb));
                ah[mi][1] = *(const u32*)(st + sw_off(r0 + 8, cb));
                ah[mi][2] = *(const u32*)(st + sw_off(r0,     cb + 16));
                ah[mi][3] = *(const u32*)(st + sw_off(r0 + 8, cb + 16));
                al[mi][0] = *(const u32*)(st + 8192 + sw_off(r0,     cb));
                al[mi][1] = *(const u32*)(st + 8192 + sw_off(r0 + 8, cb));
                al[mi][2] = *(const u32*)(st + 8192 + sw_off(r0,     cb + 16));
                al[mi][3] = *(const u32*)(st + 8192 + sw_off(r0 + 8, cb + 16));
            }
#pragma unroll
            for (int ni = 0; ni < 4; ni++) {
                int n0 = wn + ni * 8 + grp;
                bhf[ni][0] = *(const u32*)(st + 16384 + sw_off(n0, cb));
                bhf[ni][1] = *(const u32*)(st + 16384 + sw_off(n0, cb + 16));
                blf[ni][0] = *(const u32*)(st + 20480 + sw_off(n0, cb));
                blf[ni][1] = *(const u32*)(st + 20480 + sw_off(n0, cb + 16));
            }
#pragma unroll
            for (int mi = 0; mi < 2; mi++)
#pragma unroll
                for (int ni = 0; ni < 4; ni++) {
                    mma16816(acc[mi][ni], ah[mi], bhf[ni]);
                    mma16816(acc[mi][ni], ah[mi], blf[ni]);
                    mma16816(acc[mi][ni], al[mi], bhf[ni]);
                }
        }
        __syncthreads();
    }

#pragma unroll
    for (int mi = 0; mi < 2; mi++) {
#pragma unroll
        for (int ni = 0; ni < 4; ni++) {
            int row = bm + wm + mi * 16 + grp;
            int col = bn + wn + ni * 8 + tig * 2;
            *(float2*)&C[(size_t)row * N + col]       = make_float2(acc[mi][ni][0], acc[mi][ni][1]);
            *(float2*)&C[(size_t)(row + 8) * N + col] = make_float2(acc[mi][ni][2], acc[mi][ni][3]);
        }
    }
}

// ---------------------------------------------------------------------------
// RMSNorm: g_s1 slice (offset, stride 960) -> bf16 hi/lo dst
// ---------------------------------------------------------------------------
__global__ void __launch_bounds__(128) rmsnorm_kernel(int off, int dstid,
                                                      const float* __restrict__ w, int N)
{
    const float* x = g_s1 + (size_t)blockIdx.x * 960 + off;
    bf16* dh = ((dstid == 1) ? g_cqh : g_ckvh) + (size_t)blockIdx.x * N;
    bf16* dl = ((dstid == 1) ? g_cql : g_ckvl) + (size_t)blockIdx.x * N;
    int tid = threadIdx.x;

    float ss = 0.f;
    for (int i = tid; i < N; i += 128) { float v = x[i]; ss = fmaf(v, v, ss); }
#pragma unroll
    for (int o = 16; o; o >>= 1) ss += __shfl_xor_sync(0xffffffffu, ss, o);

    __shared__ float sp[4];
    if ((tid & 31) == 0) sp[tid >> 5] = ss;
    __syncthreads();
    float tot = sp[0] + sp[1] + sp[2] + sp[3];
    float sc = rsqrtf(tot / (float)N + 1e-6f);

    for (int i = tid; i < N; i += 128) {
        float v = x[i] * sc * w[i];
        bf16 h = __float2bfloat16(v);
        dh[i] = h;
        dl[i] = __float2bfloat16(v - __bfloat162float(h));
    }
}

// ---------------------------------------------------------------------------
// Assemble Q -> per-head RMSNorm -> g_qfh/l [B,H,T,64] bf16
// ---------------------------------------------------------------------------
__global__ void __launch_bounds__(512) assemble_q_kernel(const float* __restrict__ hw)
{
    int token = blockIdx.x;
    int b = token >> 11;
    int t = token & 2047;
    int tid = threadIdx.x;
    int h = tid >> 6;
    int d = tid & 63;

    const float* qn = g_qnr + (size_t)token * 512 + h * 32;
    const float* qr = g_qnr + (size_t)token * 512 + 256 + h * 32;

    float val;
    if (d < DN_) {
        val = qn[d];
    } else {
        int dr = d - DN_;
        float c = g_ropec[t * 16 + (dr & 15)];
        float s = g_ropes[t * 16 + (dr & 15)];
        val = (dr < 16) ? (qr[dr] * c - qr[dr + 16] * s)
                        : (qr[dr] * c + qr[dr - 16] * s);
    }

    float ss = val * val;
#pragma unroll
    for (int o = 16; o; o >>= 1) ss += __shfl_xor_sync(0xffffffffu, ss, o);
    __shared__ float sp[16];
    if ((tid & 31) == 0) sp[tid >> 5] = ss;
    __syncthreads();
    float tot = sp[2 * h] + sp[2 * h + 1];
    float sc = rsqrtf(tot * (1.0f / 64.0f) + 1e-6f);

    float out = val * sc * hw[d];
    size_t o = ((size_t)(b * H_ + h) * T_ + t) * HD_ + d;
    bf16 hh = __float2bfloat16(out);
    g_qfh[o] = hh;
    g_qfl[o] = __float2bfloat16(out - __bfloat162float(hh));
}

// ---------------------------------------------------------------------------
// Assemble K -> g_kfh/l [B,KVH,T,64] bf16
// ---------------------------------------------------------------------------
__global__ void __launch_bounds__(128) assemble_k_kernel(const float* __restrict__ hw)
{
    int token = blockIdx.x;
    int b = token >> 11;
    int t = token & 2047;
    int tid = threadIdx.x;
    int h = tid >> 6;
    int d = tid & 63;

    const float* kn = g_kv + (size_t)token * 192 + h * 32;
    const float* kr = g_s1 + (size_t)token * 960 + 384 + h * 32;

    float val;
    if (d < DN_) {
        val = kn[d];
    } else {
        int dr = d - DN_;
        float c = g_ropec[t * 16 + (dr & 15)];
        float s = g_ropes[t * 16 + (dr & 15)];
        val = (dr < 16) ? (kr[dr] * c - kr[dr + 16] * s)
                        : (kr[dr] * c + kr[dr - 16] * s);
    }

    float ss = val * val;
#pragma unroll
    for (int o = 16; o; o >>= 1) ss += __shfl_xor_sync(0xffffffffu, ss, o);
    __shared__ float sp[4];
    if ((tid & 31) == 0) sp[tid >> 5] = ss;
    __syncthreads();
    float tot = sp[2 * h] + sp[2 * h + 1];
    float sc = rsqrtf(tot * (1.0f / 64.0f) + 1e-6f);

    float out = val * sc * hw[d];
    size_t o = ((size_t)(b * KVH_ + h) * T_ + t) * HD_ + d;
    bf16 hh = __float2bfloat16(out);
    g_kfh[o] = hh;
    g_kfl[o] = __float2bfloat16(out - __bfloat162float(hh));
}

// ---------------------------------------------------------------------------
// Flash attention on mma.sync (bf16 split), causal, GQA, fused v_res.
// grid (T/128, B*H), 256 threads (8 warps x 16 q-rows). BN=64 keys.
// ---------------------------------------------------------------------------
#define FSC 0.125f

__global__ void __launch_bounds__(256) flash_mma()
{
    __shared__ bf16 Kh_s[64][72], Kl_s[64][72];
    __shared__ bf16 Vh_s[64][72], Vl_s[64][72];

    const int bh   = blockIdx.y;
    const int b    = bh >> 3;
    const int h    = bh & 7;
    const int kvh  = h >> 2;
    const int qs   = blockIdx.x * 128;
    const int tid  = threadIdx.x;
    const int warp = tid >> 5;
    const int lane = tid & 31;
    const int grp  = lane >> 2;
    const int tig  = lane & 3;
    const int wm   = warp * 16;

    const bf16* qhb = g_qfh + ((size_t)(b * H_ + h) * T_) * 64;
    const bf16* qlb = g_qfl + ((size_t)(b * H_ + h) * T_) * 64;
    const bf16* khb = g_kfh + ((size_t)(b * KVH_ + kvh) * T_) * 64;
    const bf16* klb = g_kfl + ((size_t)(b * KVH_ + kvh) * T_) * 64;
    const bf16* vhb = g_vth + ((size_t)(b * KVH_ + kvh) * 64) * T_;
    const bf16* vlb = g_vtl + ((size_t)(b * KVH_ + kvh) * 64) * T_;

    const int q0 = qs + wm + grp;
    const int q1 = q0 + 8;

    u32 qfh[4][4], qfl[4][4];
#pragma unroll
    for (int kst = 0; kst < 4; kst++) {
        int c0 = kst * 16 + tig * 2;
        qfh[kst][0] = *(const u32*)&qhb[(size_t)q0 * 64 + c0];
        qfh[kst][1] = *(const u32*)&qhb[(size_t)q1 * 64 + c0];
        qfh[kst][2] = *(const u32*)&qhb[(size_t)q0 * 64 + c0 + 8];
        qfh[kst][3] = *(const u32*)&qhb[(size_t)q1 * 64 + c0 + 8];
        qfl[kst][0] = *(const u32*)&qlb[(size_t)q0 * 64 + c0];
        qfl[kst][1] = *(const u32*)&qlb[(size_t)q1 * 64 + c0];
        qfl[kst][2] = *(const u32*)&qlb[(size_t)q0 * 64 + c0 + 8];
        qfl[kst][3] = *(const u32*)&qlb[(size_t)q1 * 64 + c0 + 8];
    }

    float oa[8][4];
#pragma unroll
    for (int n = 0; n < 8; n++)
#pragma unroll
        for (int i = 0; i < 4; i++) oa[n][i] = 0.f;
    float m0 = -1e30f, m1 = -1e30f, l0 = 0.f, l1 = 0.f;

    const int kend = qs + 128;
    for (int ks = 0; ks < kend; ks += 64) {
#pragma unroll
        for (int i = 0; i < 8; i++) {
            int e = tid + i * 256;
            int r = e >> 5, c2 = (e & 31) * 2;
            *(u32*)&Kh_s[r][c2] = *(const u32*)&khb[(size_t)(ks + r) * 64 + c2];
            *(u32*)&Kl_s[r][c2] = *(const u32*)&klb[(size_t)(ks + r) * 64 + c2];
            *(u32*)&Vh_s[r][c2] = *(const u32*)&vhb[(size_t)r * T_ + ks + c2];
            *(u32*)&Vl_s[r][c2] = *(const u32*)&vlb[(size_t)r * T_ + ks + c2];
        }
        __syncthreads();

        if (ks <= qs + wm + 15) {
            float sa[8][4];
#pragma unroll
            for (int n = 0; n < 8; n++)
#pragma unroll
                for (int i = 0; i < 4; i++) sa[n][i] = 0.f;

#pragma unroll
            for (int kst = 0; kst < 4; kst++) {
                int c0 = kst * 16 + tig * 2;
#pragma unroll
                for (int n = 0; n < 8; n++) {
                    int r = n * 8 + grp;
                    u32 bhf[2], blf[2];
                    bhf[0] = *(const u32*)&Kh_s[r][c0];
                    bhf[1] = *(const u32*)&Kh_s[r][c0 + 8];
                    blf[0] = *(const u32*)&Kl_s[r][c0];
                    blf[1] = *(const u32*)&Kl_s[r][c0 + 8];
                    mma16816(sa[n], qfh[kst], bhf);
                    mma16816(sa[n], qfh[kst], blf);
                    mma16816(sa[n], qfl[kst], bhf);
                }
            }

            float mx0 = m0, mx1 = m1;
#pragma unroll
            for (int n = 0; n < 8; n++) {
                int kb = ks + n * 8 + tig * 2;
                float v0 = (kb     <= q0) ? sa[n][0] * FSC : -1e30f;
                float v1 = (kb + 1 <= q0) ? sa[n][1] * FSC : -1e30f;
                float v2 = (kb     <= q1) ? sa[n][2] * FSC : -1e30f;
                float v3 = (kb + 1 <= q1) ? sa[n][3] * FSC : -1e30f;
                sa[n][0] = v0; sa[n][1] = v1; sa[n][2] = v2; sa[n][3] = v3;
                mx0 = fmaxf(mx0, fmaxf(v0, v1));
                mx1 = fmaxf(mx1, fmaxf(v2, v3));
            }
            mx0 = fmaxf(mx0, __shfl_xor_sync(0xffffffffu, mx0, 1));
            mx0 = fmaxf(mx0, __shfl_xor_sync(0xffffffffu, mx0, 2));
            mx1 = fmaxf(mx1, __shfl_xor_sync(0xffffffffu, mx1, 1));
            mx1 = fmaxf(mx1, __shfl_xor_sync(0xffffffffu, mx1, 2));

            float corr0 = __expf(m0 - mx0);
            float corr1 = __expf(m1 - mx1);
            m0 = mx0; m1 = mx1;
            l0 *= corr0; l1 *= corr1;
#pragma unroll
            for (int n = 0; n < 8; n++) {
                oa[n][0] *= corr0; oa[n][1] *= corr0;
                oa[n][2] *= corr1; oa[n][3] *= corr1;
            }

            float ls0 = 0.f, ls1 = 0.f;
#pragma unroll
            for (int n = 0; n < 8; n++) {
                float p0 = __expf(sa[n][0] - mx0);
                float p1 = __expf(sa[n][1] - mx0);
                float p2 = __expf(sa[n][2] - mx1);
                float p3 = __expf(sa[n][3] - mx1);
                sa[n][0] = p0; sa[n][1] = p1; sa[n][2] = p2; sa[n][3] = p3;
                ls0 += p0 + p1; ls1 += p2 + p3;
            }
            l0 += ls0; l1 += ls1;

#pragma unroll
            for (int kt = 0; kt < 4; kt++) {
                u32 pah[4], pal[4];
                split2(sa[2 * kt][0],     sa[2 * kt][1],     pah[0], pal[0]);
                split2(sa[2 * kt][2],     sa[2 * kt][3],     pah[1], pal[1]);
                split2(sa[2 * kt + 1][0], sa[2 * kt + 1][1], pah[2], pal[2]);
                split2(sa[2 * kt + 1][2], sa[2 * kt + 1][3], pah[3], pal[3]);
                int c0 = kt * 16 + tig * 2;
#pragma unroll
                for (int n = 0; n < 8; n++) {
                    int r = n * 8 + grp;
                    u32 bhf[2], blf[2];
                    bhf[0] = *(const u32*)&Vh_s[r][c0];
                    bhf[1] = *(const u32*)&Vh_s[r][c0 + 8];
                    blf[0] = *(const u32*)&Vl_s[r][c0];
                    blf[1] = *(const u32*)&Vl_s[r][c0 + 8];
                    mma16816(oa[n], pah, bhf);
                    mma16816(oa[n], pah, blf);
                    mma16816(oa[n], pal, bhf);
                }
            }
        }
        __syncthreads();
    }

    // quad-reduce the softmax normalizers (partials live across the lane quad)
    l0 += __shfl_xor_sync(0xffffffffu, l0, 1);
    l0 += __shfl_xor_sync(0xffffffffu, l0, 2);
    l1 += __shfl_xor_sync(0xffffffffu, l1, 1);
    l1 += __shfl_xor_sync(0xffffffffu, l1, 2);

    float inv0 = 1.0f / l0;
    float inv1 = 1.0f / l1;
    size_t row0 = (size_t)b * T_ + q0;
    size_t row1 = (size_t)b * T_ + q1;
#pragma unroll
    for (int n = 0; n < 8; n++) {
        int col = h * 64 + n * 8 + tig * 2;
        float a0 = oa[n][0] * inv0 + g_s1[row0 * 960 + 448 + col];
        float a1 = oa[n][1] * inv0 + g_s1[row0 * 960 + 448 + col + 1];
        float a2 = oa[n][2] * inv1 + g_s1[row1 * 960 + 448 + col];
        float a3 = oa[n][3] * inv1 + g_s1[row1 * 960 + 448 + col + 1];
        u32 h01, l01, h23, l23;
        split2(a0, a1, h01, l01);
        split2(a2, a3, h23, l23);
        *(u32*)&g_attnh[row0 * 512 + col] = h01;
        *(u32*)&g_attnl[row0 * 512 + col] = l01;
        *(u32*)&g_attnh[row1 * 512 + col] = h23;
        *(u32*)&g_attnl[row1 * 512 + col] = l23;
    }
}

// ---------------------------------------------------------------------------
// Launch
// ---------------------------------------------------------------------------
extern "C" void kernel_launch(void* const* d_in, const int* in_sizes, int n_in,
                              void* d_out, int out_size)
{
    const float* x       = (const float*)d_in[0];
    const float* W_DQ    = (const float*)d_in[1];
    const float* W_UQ    = (const float*)d_in[2];
    const float* W_QR    = (const float*)d_in[3];
    const float* W_DKV   = (const float*)d_in[4];
    const float* W_UK    = (const float*)d_in[5];
    const float* W_UV    = (const float*)d_in[6];
    const float* W_KR    = (const float*)d_in[7];
    const float* W_VR    = (const float*)d_in[8];
    const float* W_O     = (const float*)d_in[9];
    const float* q_ln_w  = (const float*)d_in[10];
    const float* kv_ln_w = (const float*)d_in[11];
    const float* q_hw    = (const float*)d_in[12];
    const float* k_hw    = (const float*)d_in[13];
    float* out = (float*)d_out;

    // Stage 0: one-time conversions
    conv_all<<<3552, 256>>>(W_DQ, W_UQ, W_QR, W_DKV, W_UK, W_UV, W_KR, W_VR, W_O);
    conv_x<<<BT_ * 512 / 256, 256>>>(x);
    rope_tab<<<T_ * 16 / 256, 256>>>();

    // Stage 1: all x-projections in one GEMM (N = 256+128+64+512 = 960)
    gemm_bf<<<dim3(15, 64), 256>>>(0, 0, nullptr, 0, BT_, 960, 512);

    // Stage 2: latent RMSNorms
    rmsnorm_kernel<<<BT_, 128>>>(0,   1, q_ln_w, 256);
    rmsnorm_kernel<<<BT_, 128>>>(256, 2, kv_ln_w, 128);

    // Stage 3: up-projections (merged)
    gemm_bf<<<dim3(8, 64), 256>>>(1, OFF_W2, nullptr, 1, BT_, 512, 256);
    gemm_bf<<<dim3(3, 64), 256>>>(2, OFF_W3, nullptr, 2, BT_, 192, 128);

    // Stage 4: rope + head-norm + layout; V transpose
    assemble_q_kernel<<<BT_, 512>>>(q_hw);
    assemble_k_kernel<<<BT_, 128>>>(k_hw);
    vtrans_kernel<<<dim3(T_ / 64, B_ * KVH_), 256>>>();

    // Stage 5: flash attention (tensor cores) + v_res
    flash_mma<<<dim3(T_ / 128, B_ * H_), 256>>>();

    // Stage 6: output projection -> d_out
    gemm_bf<<<dim3(8, 64), 256>>>(3, OFF_WO, out, -1, BT_, 512, 512);
}